// round 8
// baseline (speedup 1.0000x reference)
#include <cuda_runtime.h>
#include <cstdint>

// ---------------------------------------------------------------------------
// ConvKanModel, FFMA2 direct conv, x-pair packing (scheme B).
// acc = packed f32x2 over adjacent output pixels (x, x+1); activation pairs
// load directly as aligned LDS64 from planar feature planes; weights are
// pre-duplicated u64 in gmem -> broadcast LDS64, no packing MOVs.
// Per (j,ky): 96 FFMA2 vs 36 other issues (round-2 was 96:60).
// ---------------------------------------------------------------------------

#define NB      4
#define CCH     16
#define HW      512
#define PLANE   (HW*HW)
#define TOTAL   (NB*CCH*PLANE)

#define TILE    32
#define HALO    34
#define HALO2   (HALO*HALO)       // 1156
#define PL      1160              // feature plane stride (words, even)
#define NWU     1728              // weight u64 per channel: 12j*9tap*16oc
#define W_W     (12*PL)           // 13920 words
#define SMEM_WORDS (W_W + 2*NWU)  // 17376
#define SMEM_BYTES (SMEM_WORDS*4) // 69504

__device__ float g_z1[TOTAL];
__device__ float g_z2[TOTAL];
__device__ float g_m1[64], g_r1[64], g_m2[64], g_r2[64];

typedef unsigned long long u64;
__device__ u64 g_Wd[2*CCH*NWU];   // duplicated-pair weights [l][c][(j*9+tap)*16+o]

__device__ __forceinline__ void fma2(u64& d, u64 a, u64 b) {
    asm("fma.rn.f32x2 %0, %1, %2, %0;" : "+l"(d) : "l"(a), "l"(b));
}
__device__ __forceinline__ u64 packf(float lo, float hi) {
    u64 r;
    asm("mov.b64 %0, {%1, %2};" : "=l"(r) : "f"(lo), "f"(hi));
    return r;
}

// ---- weight prep: duplicated u64, layout [(j*9 + ky*3 + kx)*16 + o] -------
__global__ void prep_W(const float* __restrict__ bw1, const float* __restrict__ sw1,
                       const float* __restrict__ bw2, const float* __restrict__ sw2)
{
    const int l = blockIdx.x >> 4, c = blockIdx.x & 15;
    const float* bw = l ? bw2 : bw1;
    const float* sw = l ? sw2 : sw1;
    u64* dst = g_Wd + (size_t)(l*CCH + c) * NWU;
    for (int e = threadIdx.x; e < NWU; e += blockDim.x) {
        const int o    = e & 15;
        const int rest = e >> 4;          // 0..107
        const int kx   = rest % 3;
        const int ky   = (rest / 3) % 3;
        const int j    = rest / 9;        // 0..11
        float v;
        if (j == 0) v = bw[((o*CCH + c)*3 + ky)*3 + kx];
        else        v = sw[((o*(CCH*11) + c*11 + (j-1))*3 + ky)*3 + kx];
        const uint32_t u = __float_as_uint(v);
        dst[(j*9 + ky*3 + kx)*16 + o] = ((u64)u << 32) | (u64)u;
    }
}

// ---------------------------------------------------------------------------
// Fused KAN conv. Block: 256 threads, 32x32 tile, 16 out channels.
// tid: xp = tid&15 (x-pair), rowgrp = (tid>>4)&3 (8 rows), og = tid>>6 (4 oc).
// ---------------------------------------------------------------------------
template<bool NORM>
__global__ __launch_bounds__(256, 2)
void conv_xp(const float* __restrict__ in,
             const u64* __restrict__ gW,        // this layer's g_Wd slice
             const float* __restrict__ mean,
             const float* __restrict__ rstd,
             const float* __restrict__ alpha_p,
             float* __restrict__ out)
{
    extern __shared__ uint32_t sm[];
    float* s_act = reinterpret_cast<float*>(sm);
    u64*   s_w   = reinterpret_cast<u64*>(sm + W_W);

    const int tid    = threadIdx.x;
    const int xp     = tid & 15;
    const int rowgrp = (tid >> 4) & 3;
    const int og     = tid >> 6;
    const int bx     = blockIdx.x * TILE;
    const int by     = blockIdx.y * TILE;
    const int b      = blockIdx.z;

    const float alpha = NORM ? alpha_p[0] : 0.0f;

    u64 acc[8][4];
#pragma unroll
    for (int r = 0; r < 8; ++r)
#pragma unroll
        for (int o = 0; o < 4; ++o) acc[r][o] = 0ull;

    for (int c = 0; c < CCH; ++c) {
        __syncthreads();   // protect previous iteration's smem reads

        // ---- copy duplicated weights (uint4, L2-resident) ----
        {
            const uint4* gw4 = reinterpret_cast<const uint4*>(gW + (size_t)c * NWU);
            uint4* sw4 = reinterpret_cast<uint4*>(s_w);
#pragma unroll
            for (int i = 0; i < 4; ++i) {
                const int e = tid + i*256;
                if (e < NWU/2) sw4[e] = gw4[e];
            }
        }

        // ---- stage 12 planar feature planes over the 34x34 halo ----
        const float* inp = in + (((size_t)(b*CCH + c)) << 18);
        float mu = 0.0f, rs = 0.0f;
        if (NORM) { mu = mean[b*CCH + c]; rs = rstd[b*CCH + c]; }

#pragma unroll
        for (int it = 0; it < 5; ++it) {
            const int idx = tid + it*256;
            if (idx >= HALO2) break;
            const int iy = idx / HALO;
            const int ix = idx - iy * HALO;
            const int gy = by + iy - 1;
            const int gx = bx + ix - 1;

            float a0 = 0.0f, w0 = 0.0f, w1 = 0.0f, w2 = 0.0f, w3 = 0.0f;
            int cell = -100;
            if (gy >= 0 && gy < HW && gx >= 0 && gx < HW) {
                float x = inp[gy*HW + gx];
                if (NORM) {
                    x = (x - mu) * rs;
                    x = (x < 0.0f) ? alpha * x : x;        // prelu
                }
                a0 = x / (1.0f + __expf(-x));              // silu
                const float u  = (x + 1.75f) * 4.0f;
                const float cf = floorf(u);
                const int   ci = (int)cf;
                if (ci >= 0 && ci < 14) {
                    cell = ci;
                    const float t = u - cf, mt = 1.0f - t, t2 = t*t, t3 = t2*t;
                    w0 = mt*mt*mt * (1.0f/6.0f);
                    w1 = (3.0f*t3 - 6.0f*t2 + 4.0f) * (1.0f/6.0f);
                    w2 = (-3.0f*t3 + 3.0f*t2 + 3.0f*t + 1.0f) * (1.0f/6.0f);
                    w3 = t3 * (1.0f/6.0f);
                }
            }
            s_act[idx] = a0;                               // feature 0 = silu
#pragma unroll
            for (int j = 1; j < 12; ++j) s_act[j*PL + idx] = 0.0f;
            if (cell >= 0) {
                // stored bases 0..10 live in slots j = basis+1
                if (cell >= 3)               s_act[(cell-2)*PL + idx] = w0;
                if (cell >= 2 && cell <= 12) s_act[(cell-1)*PL + idx] = w1;
                if (cell >= 1 && cell <= 11) s_act[(cell  )*PL + idx] = w2;
                if (cell <= 10)              s_act[(cell+1)*PL + idx] = w3;
            }
        }
        __syncthreads();

        // ---- accumulate: 12 features x 3 ky; x-pair packed FFMA2 ----
#pragma unroll 1
        for (int j = 0; j < 12; ++j) {
            const float* actj = s_act + j*PL + rowgrp*8*HALO + 2*xp;
            const u64*   wj   = s_w + j*9*16 + og*4;
#pragma unroll
            for (int ky = 0; ky < 3; ++ky) {
                // 12 broadcast weight LDS64
                u64 w[3][4];
#pragma unroll
                for (int kx = 0; kx < 3; ++kx)
#pragma unroll
                    for (int o = 0; o < 4; ++o)
                        w[kx][o] = wj[(ky*3 + kx)*16 + o];

                const float* ar = actj + ky*HALO;
#pragma unroll
                for (int r = 0; r < 8; ++r) {
                    const float2 A = *reinterpret_cast<const float2*>(ar + r*HALO);
                    const float2 B = *reinterpret_cast<const float2*>(ar + r*HALO + 2);
                    const u64 pA = packf(A.x, A.y);     // kx=0 pair
                    const u64 pM = packf(A.y, B.x);     // kx=1 pair
                    const u64 pB = packf(B.x, B.y);     // kx=2 pair
#pragma unroll
                    for (int o = 0; o < 4; ++o) fma2(acc[r][o], pA, w[0][o]);
#pragma unroll
                    for (int o = 0; o < 4; ++o) fma2(acc[r][o], pM, w[1][o]);
#pragma unroll
                    for (int o = 0; o < 4; ++o) fma2(acc[r][o], pB, w[2][o]);
                }
            }
        }
    }

    // ---- epilogue: 8 rows x 4 oc, float2 stores over the x-pair ----
#pragma unroll
    for (int o = 0; o < 4; ++o) {
        const int oc = og*4 + o;
        float* op = out + (((size_t)(b*CCH + oc)) << 18);
#pragma unroll
        for (int r = 0; r < 8; ++r) {
            const int gy = by + rowgrp*8 + r;
            *reinterpret_cast<float2*>(op + (size_t)gy*HW + bx + 2*xp) =
                *reinterpret_cast<const float2*>(&acc[r][o]);
        }
    }
}

// ---------------------------------------------------------------------------
__global__ void stats_kernel(const float* __restrict__ z,
                             float* __restrict__ mean, float* __restrict__ rstd)
{
    __shared__ float sh_s[1024], sh_q[1024];
    const int bc = blockIdx.x;
    const float4* p = reinterpret_cast<const float4*>(z + (size_t)bc * PLANE);
    float s = 0.0f, q = 0.0f;
    for (int i = threadIdx.x; i < PLANE/4; i += 1024) {
        const float4 v = p[i];
        s += v.x + v.y + v.z + v.w;
        q += v.x*v.x + v.y*v.y + v.z*v.z + v.w*v.w;
    }
    sh_s[threadIdx.x] = s; sh_q[threadIdx.x] = q;
    __syncthreads();
    for (int off = 512; off > 0; off >>= 1) {
        if (threadIdx.x < off) {
            sh_s[threadIdx.x] += sh_s[threadIdx.x + off];
            sh_q[threadIdx.x] += sh_q[threadIdx.x + off];
        }
        __syncthreads();
    }
    if (threadIdx.x == 0) {
        const float m = sh_s[0] * (1.0f/PLANE);
        const float v = sh_q[0] * (1.0f/PLANE) - m*m;
        mean[bc] = m; rstd[bc] = rsqrtf(v + 1e-5f);
    }
}

__global__ void finalize_kernel(const float* __restrict__ z,
                                const float* __restrict__ mean,
                                const float* __restrict__ rstd,
                                const float* __restrict__ alpha_p,
                                float* __restrict__ out)
{
    const size_t i4 = (size_t)blockIdx.x * blockDim.x + threadIdx.x;
    if (i4 >= TOTAL/4) return;
    const int bc = (int)(i4 >> 16);
    const float alpha = alpha_p[0], m = mean[bc], rs = rstd[bc];
    float4 v = reinterpret_cast<const float4*>(z)[i4];
    float* vp = &v.x;
#pragma unroll
    for (int k = 0; k < 4; ++k) {
        float t = (vp[k] - m) * rs;
        t = (t < 0.0f) ? alpha * t : t;
        vp[k] = 1.0f / (1.0f + __expf(-t));
    }
    reinterpret_cast<float4*>(out)[i4] = v;
}

// ---------------------------------------------------------------------------
extern "C" void kernel_launch(void* const* d_in, const int* in_sizes, int n_in,
                              void* d_out, int out_size)
{
    const float* x   = (const float*)d_in[0];
    const float* bw1 = (const float*)d_in[1];
    const float* sw1 = (const float*)d_in[2];
    const float* a1  = (const float*)d_in[3];
    const float* bw2 = (const float*)d_in[4];
    const float* sw2 = (const float*)d_in[5];
    const float* a2  = (const float*)d_in[6];
    float* out = (float*)d_out;

    float *z1, *z2, *m1, *r1, *m2, *r2;
    u64* Wd;
    cudaGetSymbolAddress((void**)&z1, g_z1);
    cudaGetSymbolAddress((void**)&z2, g_z2);
    cudaGetSymbolAddress((void**)&m1, g_m1);
    cudaGetSymbolAddress((void**)&r1, g_r1);
    cudaGetSymbolAddress((void**)&m2, g_m2);
    cudaGetSymbolAddress((void**)&r2, g_r2);
    cudaGetSymbolAddress((void**)&Wd, g_Wd);

    cudaFuncSetAttribute(conv_xp<false>,
                         cudaFuncAttributeMaxDynamicSharedMemorySize, SMEM_BYTES);
    cudaFuncSetAttribute(conv_xp<true>,
                         cudaFuncAttributeMaxDynamicSharedMemorySize, SMEM_BYTES);

    prep_W<<<32, 256>>>(bw1, sw1, bw2, sw2);

    const dim3 grid(HW/TILE, HW/TILE, NB);   // 16 x 16 x 4

    conv_xp<false><<<grid, 256, SMEM_BYTES>>>(
        x, Wd, nullptr, nullptr, nullptr, z1);
    stats_kernel<<<NB*CCH, 1024>>>(z1, m1, r1);

    conv_xp<true><<<grid, 256, SMEM_BYTES>>>(
        z1, Wd + (size_t)CCH*NWU, m1, r1, a1, z2);
    stats_kernel<<<NB*CCH, 1024>>>(z2, m2, r2);

    finalize_kernel<<<(TOTAL/4 + 255)/256, 256>>>(z2, m2, r2, a2, out);
}

// round 9
// speedup vs baseline: 1.3725x; 1.3725x over previous
#include <cuda_runtime.h>
#include <cstdint>

// ---------------------------------------------------------------------------
// ConvKanModel: round-2 FFMA2 oc-pair conv (best known) made persistent with
// atomic work-stealing over the 1024-tile queue to remove wave quantization
// (1024 CTAs / ~296 resident = 3.46 waves -> 86% slot use; stealing -> ~95%).
// Inner loop unchanged: thread = 8 px x 8 oc, acc packed f32x2 over oc pairs,
// weights as broadcast LDS64, acts LDS32 + mov.b64 pack (1:4 alu:fma ratio).
// ---------------------------------------------------------------------------

#define NB      4
#define CCH     16
#define KB      11
#define JF      12
#define HW      512
#define PLANE   (HW*HW)
#define TOTAL   (NB*CCH*PLANE)

#define TILE    32
#define HALO    34
#define HALO2   (HALO*HALO)       // 1156
#define NW      (JF*3*3*CCH)      // 1728
#define NTILES  (16*16*NB)        // 1024
#define SMEM_BYTES ((JF*HALO2 + NW) * 4)   // 62400

#define GRID_P  296               // persistent CTAs (~2 per SM)

__device__ float g_z1[TOTAL];
__device__ float g_z2[TOTAL];
__device__ float g_m1[64], g_r1[64], g_m2[64], g_r2[64];
__device__ unsigned int g_ctr[2];

typedef unsigned long long u64;

__device__ __forceinline__ u64 pack2(float x) {
    u64 r;
    asm("mov.b64 %0, {%1, %1};" : "=l"(r) : "f"(x));
    return r;
}
__device__ __forceinline__ void fma2(u64& d, u64 a, u64 b) {
    asm("fma.rn.f32x2 %0, %1, %2, %0;" : "+l"(d) : "l"(a), "l"(b));
}

__global__ void reset_ctr() {
    if (threadIdx.x < 2) g_ctr[threadIdx.x] = 0u;
}

// ---------------------------------------------------------------------------
// Persistent fused KAN conv. 256 threads; steals 32x32 tiles (16 oc each).
// Thread: 8 pixels (one column, 8 consecutive rows) x 8 out channels.
// ---------------------------------------------------------------------------
template<bool NORM>
__global__ __launch_bounds__(256, 2)
void conv_kan_p(const float* __restrict__ in,
                const float* __restrict__ base_w,    // [16][16][3][3]
                const float* __restrict__ spline_w,  // [16][176][3][3]
                const float* __restrict__ mean,
                const float* __restrict__ rstd,
                const float* __restrict__ alpha_p,
                float* __restrict__ out)
{
    extern __shared__ float smem[];
    float* s_act = smem;                 // [JF][HALO2]
    float* s_w   = smem + JF*HALO2;      // [JF][3][3][16]
    __shared__ int s_tile;

    const int tid    = threadIdx.x;
    const int col    = tid & 31;
    const int rowgrp = (tid >> 5) & 3;
    const int ohalf  = tid >> 7;
    const float alpha = NORM ? alpha_p[0] : 0.0f;
    const int ctr_idx = NORM ? 1 : 0;

    for (;;) {
        __syncthreads();   // protect s_tile + previous tile's smem reads
        if (tid == 0) s_tile = (int)atomicAdd(&g_ctr[ctr_idx], 1u);
        __syncthreads();
        const int t = s_tile;
        if (t >= NTILES) break;

        const int bx = (t & 15) * TILE;
        const int by = ((t >> 4) & 15) * TILE;
        const int b  = t >> 8;

        u64 acc[8][4];
#pragma unroll
        for (int r = 0; r < 8; ++r)
#pragma unroll
            for (int p = 0; p < 4; ++p) acc[r][p] = 0ull;

        for (int c = 0; c < CCH; ++c) {
            __syncthreads();   // protect previous channel's smem reads

            // ---- build activation tile for input channel c ----
            const float* inp = in + ((size_t)(b*CCH + c)) * PLANE;
            float mu = 0.0f, rs = 0.0f;
            if (NORM) { mu = mean[b*CCH + c]; rs = rstd[b*CCH + c]; }

            for (int idx = tid; idx < HALO2; idx += 256) {
                const int iy = idx / HALO;
                const int ix = idx - iy * HALO;
                const int gy = by + iy - 1;
                const int gx = bx + ix - 1;

                float a0 = 0.0f, w0 = 0.0f, w1 = 0.0f, w2 = 0.0f, w3 = 0.0f;
                int cell = -100;
                if (gy >= 0 && gy < HW && gx >= 0 && gx < HW) {
                    float x = inp[gy*HW + gx];
                    if (NORM) {
                        x = (x - mu) * rs;
                        x = (x < 0.0f) ? alpha * x : x;   // prelu
                    }
                    a0 = x / (1.0f + __expf(-x));          // silu
                    const float u  = (x + 1.75f) * 4.0f;
                    const float cf = floorf(u);
                    const int ci = (int)cf;
                    if (ci >= 0 && ci < 14) {
                        cell = ci;
                        const float tt = u - cf;
                        const float mt = 1.0f - tt;
                        const float t2 = tt*tt, t3 = t2*tt;
                        w0 = mt*mt*mt * (1.0f/6.0f);
                        w1 = (3.0f*t3 - 6.0f*t2 + 4.0f) * (1.0f/6.0f);
                        w2 = (-3.0f*t3 + 3.0f*t2 + 3.0f*tt + 1.0f) * (1.0f/6.0f);
                        w3 = t3 * (1.0f/6.0f);
                    }
                }
                s_act[idx] = a0;                     // feature 0 = silu
#pragma unroll
                for (int j = 1; j < JF; ++j) s_act[j*HALO2 + idx] = 0.0f;
                if (cell >= 0) {
                    if (cell >= 3)               s_act[(cell-2)*HALO2 + idx] = w0;
                    if (cell >= 2 && cell <= 12) s_act[(cell-1)*HALO2 + idx] = w1;
                    if (cell >= 1 && cell <= 11) s_act[(cell  )*HALO2 + idx] = w2;
                    if (cell <= 10)              s_act[(cell+1)*HALO2 + idx] = w3;
                }
            }

            // ---- load combined weights for channel c: [j][ky][kx][o] ----
            for (int idx = tid; idx < NW; idx += 256) {
                const int o    = idx & 15;
                const int rest = idx >> 4;
                const int kx   = rest % 3;
                const int ky   = (rest / 3) % 3;
                const int j    = rest / 9;
                float w;
                if (j == 0) w = base_w[((o*CCH + c)*3 + ky)*3 + kx];
                else        w = spline_w[((o*(CCH*KB) + (c*KB + j - 1))*3 + ky)*3 + kx];
                s_w[((j*3 + ky)*3 + kx)*CCH + o] = w;
            }
            __syncthreads();

            // ---- accumulate: 12 features x 9 taps, oc-pair packed ----
            const int rbase = rowgrp * 8;
#pragma unroll 1
            for (int j = 0; j < JF; ++j) {
                const float* actj = s_act + j*HALO2;
                const float* wj   = s_w + j*9*CCH + ohalf*8;
#pragma unroll
                for (int ky = 0; ky < 3; ++ky) {
                    // hoist 12 weight pairs for this (j,ky)
                    u64 wv[3][4];
#pragma unroll
                    for (int kx = 0; kx < 3; ++kx) {
                        const u64* wp =
                            reinterpret_cast<const u64*>(wj + (ky*3 + kx)*CCH);
#pragma unroll
                        for (int p = 0; p < 4; ++p) wv[kx][p] = wp[p];
                    }
                    const float* arow = actj + (rbase + ky)*HALO + col;
#pragma unroll
                    for (int kx = 0; kx < 3; ++kx) {
#pragma unroll
                        for (int r = 0; r < 8; ++r) {
                            const u64 a2 = pack2(arow[r*HALO + kx]);
#pragma unroll
                            for (int p = 0; p < 4; ++p)
                                fma2(acc[r][p], a2, wv[kx][p]);
                        }
                    }
                }
            }
        }

        // ---- epilogue: unpack & write 8 pixels x 8 out channels ----
#pragma unroll
        for (int p = 0; p < 4; ++p) {
            const int o0 = ohalf*8 + 2*p;
            float* op0 = out + ((size_t)(b*CCH + o0    )) * PLANE;
            float* op1 = out + ((size_t)(b*CCH + o0 + 1)) * PLANE;
#pragma unroll
            for (int r = 0; r < 8; ++r) {
                const int gy = by + rowgrp*8 + r;
                const uint32_t lo = (uint32_t)(acc[r][p] & 0xffffffffull);
                const uint32_t hi = (uint32_t)(acc[r][p] >> 32);
                op0[gy*HW + bx + col] = __uint_as_float(lo);
                op1[gy*HW + bx + col] = __uint_as_float(hi);
            }
        }
    }
}

// ---------------------------------------------------------------------------
__global__ void stats_kernel(const float* __restrict__ z,
                             float* __restrict__ mean, float* __restrict__ rstd)
{
    __shared__ float sh_s[1024], sh_q[1024];
    const int bc = blockIdx.x;
    const float4* p = reinterpret_cast<const float4*>(z + (size_t)bc * PLANE);
    float s = 0.0f, q = 0.0f;
    for (int i = threadIdx.x; i < PLANE/4; i += 1024) {
        const float4 v = p[i];
        s += v.x + v.y + v.z + v.w;
        q += v.x*v.x + v.y*v.y + v.z*v.z + v.w*v.w;
    }
    sh_s[threadIdx.x] = s; sh_q[threadIdx.x] = q;
    __syncthreads();
    for (int off = 512; off > 0; off >>= 1) {
        if (threadIdx.x < off) {
            sh_s[threadIdx.x] += sh_s[threadIdx.x + off];
            sh_q[threadIdx.x] += sh_q[threadIdx.x + off];
        }
        __syncthreads();
    }
    if (threadIdx.x == 0) {
        const float m = sh_s[0] * (1.0f/PLANE);
        const float v = sh_q[0] * (1.0f/PLANE) - m*m;
        mean[bc] = m; rstd[bc] = rsqrtf(v + 1e-5f);
    }
}

__global__ void finalize_kernel(const float* __restrict__ z,
                                const float* __restrict__ mean,
                                const float* __restrict__ rstd,
                                const float* __restrict__ alpha_p,
                                float* __restrict__ out)
{
    const size_t i4 = (size_t)blockIdx.x * blockDim.x + threadIdx.x;
    if (i4 >= TOTAL/4) return;
    const int bc = (int)(i4 >> 16);
    const float alpha = alpha_p[0], m = mean[bc], rs = rstd[bc];
    float4 v = reinterpret_cast<const float4*>(z)[i4];
    float* vp = &v.x;
#pragma unroll
    for (int k = 0; k < 4; ++k) {
        float t = (vp[k] - m) * rs;
        t = (t < 0.0f) ? alpha * t : t;
        vp[k] = 1.0f / (1.0f + __expf(-t));
    }
    reinterpret_cast<float4*>(out)[i4] = v;
}

// ---------------------------------------------------------------------------
extern "C" void kernel_launch(void* const* d_in, const int* in_sizes, int n_in,
                              void* d_out, int out_size)
{
    const float* x   = (const float*)d_in[0];
    const float* bw1 = (const float*)d_in[1];
    const float* sw1 = (const float*)d_in[2];
    const float* a1  = (const float*)d_in[3];
    const float* bw2 = (const float*)d_in[4];
    const float* sw2 = (const float*)d_in[5];
    const float* a2  = (const float*)d_in[6];
    float* out = (float*)d_out;

    float *z1, *z2, *m1, *r1, *m2, *r2;
    cudaGetSymbolAddress((void**)&z1, g_z1);
    cudaGetSymbolAddress((void**)&z2, g_z2);
    cudaGetSymbolAddress((void**)&m1, g_m1);
    cudaGetSymbolAddress((void**)&r1, g_r1);
    cudaGetSymbolAddress((void**)&m2, g_m2);
    cudaGetSymbolAddress((void**)&r2, g_r2);

    cudaFuncSetAttribute(conv_kan_p<false>,
                         cudaFuncAttributeMaxDynamicSharedMemorySize, SMEM_BYTES);
    cudaFuncSetAttribute(conv_kan_p<true>,
                         cudaFuncAttributeMaxDynamicSharedMemorySize, SMEM_BYTES);

    reset_ctr<<<1, 32>>>();

    conv_kan_p<false><<<GRID_P, 256, SMEM_BYTES>>>(
        x, bw1, sw1, nullptr, nullptr, nullptr, z1);
    stats_kernel<<<NB*CCH, 1024>>>(z1, m1, r1);

    conv_kan_p<true><<<GRID_P, 256, SMEM_BYTES>>>(
        z1, bw2, sw2, m1, r1, a1, z2);
    stats_kernel<<<NB*CCH, 1024>>>(z2, m2, r2);

    finalize_kernel<<<(TOTAL/4 + 255)/256, 256>>>(z2, m2, r2, a2, out);
}

// round 10
// speedup vs baseline: 1.4129x; 1.0294x over previous
#include <cuda_runtime.h>
#include <cstdint>

// ---------------------------------------------------------------------------
// ConvKanModel: persistent FFMA2 oc-pair conv, re-blocked for occupancy 3.
// Thread = 4 px x 8 oc (16 u64 acc = 32 regs, vs 64 before) -> <=85 regs ->
// 3 CTAs/SM (6 warps/SMSP) to absorb the latency stalls that left the fma
// pipe 31% idle at 2 CTAs. Tile 32x16, halo 34x18, smem 36.3KB (3x fits).
// fma-pipe floor per tile-channel unchanged; work-stealing over 2048 tiles.
// ---------------------------------------------------------------------------

#define NB      4
#define CCH     16
#define KB      11
#define JF      12
#define HW      512
#define PLANE   (HW*HW)
#define TOTAL   (NB*CCH*PLANE)

#define TW      32                // tile width
#define TH      16                // tile height
#define HALOW   34
#define HALOH   18
#define HALO2   (HALOW*HALOH)     // 612
#define NW      (JF*3*3*CCH)      // 1728
#define NTILES  ((HW/TW)*(HW/TH)*NB)   // 16*32*4 = 2048
#define SMEM_BYTES ((JF*HALO2 + NW) * 4)   // 36288

#define GRID_P  444               // persistent CTAs (3 per SM)

__device__ float g_z1[TOTAL];
__device__ float g_z2[TOTAL];
__device__ float g_m1[64], g_r1[64], g_m2[64], g_r2[64];
__device__ unsigned int g_ctr[2];

typedef unsigned long long u64;

__device__ __forceinline__ u64 pack2(float x) {
    u64 r;
    asm("mov.b64 %0, {%1, %1};" : "=l"(r) : "f"(x));
    return r;
}
__device__ __forceinline__ void fma2(u64& d, u64 a, u64 b) {
    asm("fma.rn.f32x2 %0, %1, %2, %0;" : "+l"(d) : "l"(a), "l"(b));
}

__global__ void reset_ctr() {
    if (threadIdx.x < 2) g_ctr[threadIdx.x] = 0u;
}

// ---------------------------------------------------------------------------
// Persistent fused KAN conv. 256 threads; steals 32x16 tiles (16 oc each).
// tid: col = tid&31, rowgrp = (tid>>5)&3 (4 rows each), ohalf = tid>>7.
// ---------------------------------------------------------------------------
template<bool NORM>
__global__ __launch_bounds__(256, 3)
void conv_kan_p(const float* __restrict__ in,
                const float* __restrict__ base_w,    // [16][16][3][3]
                const float* __restrict__ spline_w,  // [16][176][3][3]
                const float* __restrict__ mean,
                const float* __restrict__ rstd,
                const float* __restrict__ alpha_p,
                float* __restrict__ out)
{
    extern __shared__ float smem[];
    float* s_act = smem;                 // [JF][612]
    float* s_w   = smem + JF*HALO2;      // [JF][3][3][16]
    __shared__ int s_tile;

    const int tid    = threadIdx.x;
    const int col    = tid & 31;
    const int rowgrp = (tid >> 5) & 3;
    const int ohalf  = tid >> 7;
    const float alpha = NORM ? alpha_p[0] : 0.0f;
    const int ctr_idx = NORM ? 1 : 0;

    for (;;) {
        __syncthreads();   // protect s_tile + previous tile's smem reads
        if (tid == 0) s_tile = (int)atomicAdd(&g_ctr[ctr_idx], 1u);
        __syncthreads();
        const int t = s_tile;
        if (t >= NTILES) break;

        const int bx = (t & 15) * TW;
        const int by = ((t >> 4) & 31) * TH;
        const int b  = t >> 9;

        u64 acc[4][4];
#pragma unroll
        for (int r = 0; r < 4; ++r)
#pragma unroll
            for (int p = 0; p < 4; ++p) acc[r][p] = 0ull;

        for (int c = 0; c < CCH; ++c) {
            __syncthreads();   // protect previous channel's smem reads

            // ---- build activation tile for input channel c ----
            const float* inp = in + ((size_t)(b*CCH + c)) * PLANE;
            float mu = 0.0f, rs = 0.0f;
            if (NORM) { mu = mean[b*CCH + c]; rs = rstd[b*CCH + c]; }

#pragma unroll
            for (int it = 0; it < 3; ++it) {
                const int idx = tid + it*256;
                if (idx >= HALO2) break;
                const int iy = idx / HALOW;
                const int ix = idx - iy * HALOW;
                const int gy = by + iy - 1;
                const int gx = bx + ix - 1;

                float a0 = 0.0f, w0 = 0.0f, w1 = 0.0f, w2 = 0.0f, w3 = 0.0f;
                int cell = -100;
                if (gy >= 0 && gy < HW && gx >= 0 && gx < HW) {
                    float x = inp[gy*HW + gx];
                    if (NORM) {
                        x = (x - mu) * rs;
                        x = (x < 0.0f) ? alpha * x : x;   // prelu
                    }
                    a0 = x / (1.0f + __expf(-x));          // silu
                    const float u  = (x + 1.75f) * 4.0f;
                    const float cf = floorf(u);
                    const int ci = (int)cf;
                    if (ci >= 0 && ci < 14) {
                        cell = ci;
                        const float tt = u - cf;
                        const float mt = 1.0f - tt;
                        const float t2 = tt*tt, t3 = t2*tt;
                        w0 = mt*mt*mt * (1.0f/6.0f);
                        w1 = (3.0f*t3 - 6.0f*t2 + 4.0f) * (1.0f/6.0f);
                        w2 = (-3.0f*t3 + 3.0f*t2 + 3.0f*tt + 1.0f) * (1.0f/6.0f);
                        w3 = t3 * (1.0f/6.0f);
                    }
                }
                s_act[idx] = a0;                     // feature 0 = silu
#pragma unroll
                for (int j = 1; j < JF; ++j) s_act[j*HALO2 + idx] = 0.0f;
                if (cell >= 0) {
                    // stored bases 0..10 live in slots j = basis+1
                    if (cell >= 3)               s_act[(cell-2)*HALO2 + idx] = w0;
                    if (cell >= 2 && cell <= 12) s_act[(cell-1)*HALO2 + idx] = w1;
                    if (cell >= 1 && cell <= 11) s_act[(cell  )*HALO2 + idx] = w2;
                    if (cell <= 10)              s_act[(cell+1)*HALO2 + idx] = w3;
                }
            }

            // ---- load combined weights for channel c: [j][ky][kx][o] ----
#pragma unroll
            for (int it = 0; it < 7; ++it) {
                const int idx = tid + it*256;
                if (idx >= NW) break;
                const int o    = idx & 15;
                const int rest = idx >> 4;
                const int kx   = rest % 3;
                const int ky   = (rest / 3) % 3;
                const int j    = rest / 9;
                float w;
                if (j == 0) w = base_w[((o*CCH + c)*3 + ky)*3 + kx];
                else        w = spline_w[((o*(CCH*KB) + (c*KB + j - 1))*3 + ky)*3 + kx];
                s_w[((j*3 + ky)*3 + kx)*CCH + o] = w;
            }
            __syncthreads();

            // ---- accumulate: 12 features x 9 taps, oc-pair packed ----
            const int rbase = rowgrp * 4;
#pragma unroll 1
            for (int j = 0; j < JF; ++j) {
                const float* actj = s_act + j*HALO2;
                const float* wj   = s_w + j*9*CCH + ohalf*8;
#pragma unroll
                for (int ky = 0; ky < 3; ++ky) {
                    // hoist 12 weight pairs for this (j,ky)
                    u64 wv[3][4];
#pragma unroll
                    for (int kx = 0; kx < 3; ++kx) {
                        const u64* wp =
                            reinterpret_cast<const u64*>(wj + (ky*3 + kx)*CCH);
#pragma unroll
                        for (int p = 0; p < 4; ++p) wv[kx][p] = wp[p];
                    }
                    const float* arow = actj + (rbase + ky)*HALOW + col;
#pragma unroll
                    for (int kx = 0; kx < 3; ++kx) {
#pragma unroll
                        for (int r = 0; r < 4; ++r) {
                            const u64 a2 = pack2(arow[r*HALOW + kx]);
#pragma unroll
                            for (int p = 0; p < 4; ++p)
                                fma2(acc[r][p], a2, wv[kx][p]);
                        }
                    }
                }
            }
        }

        // ---- epilogue: unpack & write 4 pixels x 8 out channels ----
#pragma unroll
        for (int p = 0; p < 4; ++p) {
            const int o0 = ohalf*8 + 2*p;
            float* op0 = out + ((size_t)(b*CCH + o0    )) * PLANE;
            float* op1 = out + ((size_t)(b*CCH + o0 + 1)) * PLANE;
#pragma unroll
            for (int r = 0; r < 4; ++r) {
                const int gy = by + rowgrp*4 + r;
                const uint32_t lo = (uint32_t)(acc[r][p] & 0xffffffffull);
                const uint32_t hi = (uint32_t)(acc[r][p] >> 32);
                op0[gy*HW + bx + col] = __uint_as_float(lo);
                op1[gy*HW + bx + col] = __uint_as_float(hi);
            }
        }
    }
}

// ---------------------------------------------------------------------------
__global__ void stats_kernel(const float* __restrict__ z,
                             float* __restrict__ mean, float* __restrict__ rstd)
{
    __shared__ float sh_s[1024], sh_q[1024];
    const int bc = blockIdx.x;
    const float4* p = reinterpret_cast<const float4*>(z + (size_t)bc * PLANE);
    float s = 0.0f, q = 0.0f;
    for (int i = threadIdx.x; i < PLANE/4; i += 1024) {
        const float4 v = p[i];
        s += v.x + v.y + v.z + v.w;
        q += v.x*v.x + v.y*v.y + v.z*v.z + v.w*v.w;
    }
    sh_s[threadIdx.x] = s; sh_q[threadIdx.x] = q;
    __syncthreads();
    for (int off = 512; off > 0; off >>= 1) {
        if (threadIdx.x < off) {
            sh_s[threadIdx.x] += sh_s[threadIdx.x + off];
            sh_q[threadIdx.x] += sh_q[threadIdx.x + off];
        }
        __syncthreads();
    }
    if (threadIdx.x == 0) {
        const float m = sh_s[0] * (1.0f/PLANE);
        const float v = sh_q[0] * (1.0f/PLANE) - m*m;
        mean[bc] = m; rstd[bc] = rsqrtf(v + 1e-5f);
    }
}

__global__ void finalize_kernel(const float* __restrict__ z,
                                const float* __restrict__ mean,
                                const float* __restrict__ rstd,
                                const float* __restrict__ alpha_p,
                                float* __restrict__ out)
{
    const size_t i4 = (size_t)blockIdx.x * blockDim.x + threadIdx.x;
    if (i4 >= TOTAL/4) return;
    const int bc = (int)(i4 >> 16);
    const float alpha = alpha_p[0], m = mean[bc], rs = rstd[bc];
    float4 v = reinterpret_cast<const float4*>(z)[i4];
    float* vp = &v.x;
#pragma unroll
    for (int k = 0; k < 4; ++k) {
        float t = (vp[k] - m) * rs;
        t = (t < 0.0f) ? alpha * t : t;
        vp[k] = 1.0f / (1.0f + __expf(-t));
    }
    reinterpret_cast<float4*>(out)[i4] = v;
}

// ---------------------------------------------------------------------------
extern "C" void kernel_launch(void* const* d_in, const int* in_sizes, int n_in,
                              void* d_out, int out_size)
{
    const float* x   = (const float*)d_in[0];
    const float* bw1 = (const float*)d_in[1];
    const float* sw1 = (const float*)d_in[2];
    const float* a1  = (const float*)d_in[3];
    const float* bw2 = (const float*)d_in[4];
    const float* sw2 = (const float*)d_in[5];
    const float* a2  = (const float*)d_in[6];
    float* out = (float*)d_out;

    float *z1, *z2, *m1, *r1, *m2, *r2;
    cudaGetSymbolAddress((void**)&z1, g_z1);
    cudaGetSymbolAddress((void**)&z2, g_z2);
    cudaGetSymbolAddress((void**)&m1, g_m1);
    cudaGetSymbolAddress((void**)&r1, g_r1);
    cudaGetSymbolAddress((void**)&m2, g_m2);
    cudaGetSymbolAddress((void**)&r2, g_r2);

    cudaFuncSetAttribute(conv_kan_p<false>,
                         cudaFuncAttributeMaxDynamicSharedMemorySize, SMEM_BYTES);
    cudaFuncSetAttribute(conv_kan_p<true>,
                         cudaFuncAttributeMaxDynamicSharedMemorySize, SMEM_BYTES);

    reset_ctr<<<1, 32>>>();

    conv_kan_p<false><<<GRID_P, 256, SMEM_BYTES>>>(
        x, bw1, sw1, nullptr, nullptr, nullptr, z1);
    stats_kernel<<<NB*CCH, 1024>>>(z1, m1, r1);

    conv_kan_p<true><<<GRID_P, 256, SMEM_BYTES>>>(
        z1, bw2, sw2, m1, r1, a1, z2);
    stats_kernel<<<NB*CCH, 1024>>>(z2, m2, r2);

    finalize_kernel<<<(TOTAL/4 + 255)/256, 256>>>(z2, m2, r2, a2, out);
}